// round 11
// baseline (speedup 1.0000x reference)
#include <cuda_runtime.h>
#include <cuda_bf16.h>
#include <cstdint>

// ============================================================================
// Problem constants
// ============================================================================
#define DDIM 768
#define NTOT 16384
#define KAPPA 0.5f

#define KSPLIT 14
#define KGRP 7               // ksplits per GEMM launch (2 launches)
#define NPAIRS 21            // 6*7/2 upper-triangle 128x128 tiles
#define BM 128
#define BK 64
#define STAGES 3
#define NCHUNK_TOT (NTOT / BK)          // 256
#define TILE_BYTES (BK * 256)           // 16 KB: [k=64][m=128] bf16, 256B rows
#define STAGE_BYTES (2 * TILE_BYTES)    // 32 KB (A + B)
#define GEMM_SMEM (STAGES * STAGE_BYTES)  // 98304 -> 2 CTAs/SM

// convert: each thread converts 16 elements (2 uint4 outputs).
// Total threads = NTOT*DDIM/16 = 786432; half = 393216 threads = 1536 blocks.
#define CVT_THREADS_HALF ((size_t)NTOT * DDIM / 16 / 2)     // 393216
#define CVT_BLOCKS_HALF  ((int)(CVT_THREADS_HALF / 256))    // 1536

// ============================================================================
// Scratch (device globals — no allocations allowed)
// ============================================================================
__device__ __align__(1024) __nv_bfloat16 g_xbf[(size_t)NTOT * DDIM];        // 25.2 MB, same layout as x
__device__ __align__(16)   float g_partials[(size_t)KSPLIT * DDIM * DDIM];  // 33 MB

__constant__ unsigned char c_pairs[NPAIRS * 2] = {
    0,0, 0,1, 0,2, 0,3, 0,4, 0,5,
    1,1, 1,2, 1,3, 1,4, 1,5,
    2,2, 2,3, 2,4, 2,5,
    3,3, 3,4, 3,5,
    4,4, 4,5,
    5,5
};

// ============================================================================
// Helpers
// ============================================================================
__device__ __forceinline__ uint32_t smem_u32(const void* p) {
    uint32_t a;
    asm("{ .reg .u64 t; cvta.to.shared.u64 t, %1; cvt.u32.u64 %0, t; }" : "=r"(a) : "l"(p));
    return a;
}

__device__ __forceinline__ void cp_async16(uint32_t dst, const void* src) {
    asm volatile("cp.async.cg.shared.global [%0], [%1], 16;" :: "r"(dst), "l"(src));
}
__device__ __forceinline__ void cp_commit() {
    asm volatile("cp.async.commit_group;");
}
template <int N>
__device__ __forceinline__ void cp_wait() {
    asm volatile("cp.async.wait_group %0;" :: "n"(N));
}

__device__ __forceinline__ void ldmatrix_x4_t(uint32_t& r0, uint32_t& r1, uint32_t& r2,
                                              uint32_t& r3, uint32_t addr) {
    asm volatile("ldmatrix.sync.aligned.m8n8.x4.trans.shared.b16 {%0,%1,%2,%3}, [%4];"
                 : "=r"(r0), "=r"(r1), "=r"(r2), "=r"(r3) : "r"(addr));
}

__device__ __forceinline__ void mma16816(float* c, uint32_t a0, uint32_t a1, uint32_t a2,
                                         uint32_t a3, uint32_t b0, uint32_t b1) {
    asm volatile(
        "mma.sync.aligned.m16n8k16.row.col.f32.bf16.bf16.f32 "
        "{%0,%1,%2,%3}, {%4,%5,%6,%7}, {%8,%9}, {%0,%1,%2,%3};"
        : "+f"(c[0]), "+f"(c[1]), "+f"(c[2]), "+f"(c[3])
        : "r"(a0), "r"(a1), "r"(a2), "r"(a3), "r"(b0), "r"(b1));
}

__device__ __forceinline__ uint32_t pack_bf16x2(float lo, float hi) {
    __nv_bfloat162 p = __float22bfloat162_rn(make_float2(lo, hi));
    return *reinterpret_cast<uint32_t*>(&p);
}

// ============================================================================
// Kernel 1: streaming fp32 -> bf16 convert over a k-range half.
// base = starting THREAD index (each thread = 16 elements = 2 uint4 out).
// ============================================================================
__global__ __launch_bounds__(256) void convert_kernel(const float* __restrict__ x,
                                                      size_t base) {
    size_t idx = base + (size_t)blockIdx.x * 256 + threadIdx.x;
    const float4* src = reinterpret_cast<const float4*>(x) + idx * 4;
    float4 v0 = __ldcs(src + 0);
    float4 v1 = __ldcs(src + 1);
    float4 v2 = __ldcs(src + 2);
    float4 v3 = __ldcs(src + 3);
    uint4 o0, o1;
    o0.x = pack_bf16x2(v0.x, v0.y);
    o0.y = pack_bf16x2(v0.z, v0.w);
    o0.z = pack_bf16x2(v1.x, v1.y);
    o0.w = pack_bf16x2(v1.z, v1.w);
    o1.x = pack_bf16x2(v2.x, v2.y);
    o1.y = pack_bf16x2(v2.z, v2.w);
    o1.z = pack_bf16x2(v3.x, v3.y);
    o1.w = pack_bf16x2(v3.z, v3.w);
    uint4* dst = reinterpret_cast<uint4*>(g_xbf) + idx * 2;
    dst[0] = o0;
    dst[1] = o1;
}

// ============================================================================
// Kernel 2: symmetric bf16 SYRK partials via mma.sync (HMMA) — R9-proven
// mainloop. One launch covers KGRP=7 ksplits (147 CTAs); ks_base selects the
// k-range half so the second half's convert can overlap the first half's GEMM.
// ============================================================================
__global__ void __launch_bounds__(256, 2) gemm_kernel(int ks_base) {
    extern __shared__ __align__(1024) char smem[];
    uint32_t sbase = smem_u32(smem);
    int tid = threadIdx.x;
    int lane = tid & 31;
    int wid = tid >> 5;
    int pair = blockIdx.x % NPAIRS;
    int ks = ks_base + blockIdx.x / NPAIRS;
    int tm = c_pairs[pair * 2];
    int tn = c_pairs[pair * 2 + 1];
    int m0 = tm * BM;
    int n0 = tn * BM;
    bool diag = (tm == tn);
    int kc0 = (ks * NCHUNK_TOT) / KSPLIT;
    int kc1 = ((ks + 1) * NCHUNK_TOT) / KSPLIT;
    int nch = kc1 - kc0;
    int warp_m = wid & 1;       // 0..1
    int warp_n = wid >> 1;      // 0..3

#define LOAD_STAGE(st, kc)                                                              \
    do {                                                                                \
        uint32_t s_ = sbase + (uint32_t)(st) * STAGE_BYTES;                             \
        const __nv_bfloat16* gk = g_xbf + (size_t)((kc) * BK) * DDIM;                   \
        _Pragma("unroll")                                                               \
        for (int i_ = 0; i_ < 4; i_++) {                                                \
            int idx_ = tid + i_ * 256;                                                  \
            int r_ = idx_ >> 4, c_ = idx_ & 15;                                         \
            uint32_t off_ = (uint32_t)r_ * 256 + (uint32_t)((c_ ^ (r_ & 7)) << 4);      \
            const __nv_bfloat16* gr = gk + (size_t)r_ * DDIM + c_ * 8;                  \
            cp_async16(s_ + off_, gr + m0);                                             \
            if (!diag) cp_async16(s_ + TILE_BYTES + off_, gr + n0);                     \
        }                                                                               \
        cp_commit();                                                                    \
    } while (0)

    // prologue: fill STAGES-1 stages
#pragma unroll
    for (int s = 0; s < STAGES - 1; s++) {
        LOAD_STAGE(s, kc0 + s);
    }

    float acc[4][4][4];
#pragma unroll
    for (int i = 0; i < 4; i++)
#pragma unroll
        for (int j = 0; j < 4; j++)
#pragma unroll
            for (int q = 0; q < 4; q++) acc[i][j][q] = 0.f;

    // ldmatrix.trans lane address components (proven in R5):
    // A frag (m16k16): krow = k_off + (l&7) + ((l>>4)<<3), mchunk = m/8 + ((l>>3)&1)
    // B frag (two n8):  krow = k_off + (l&15),             nchunk = n/8 + (l>>4)
    int a_kl = (lane & 7) + ((lane >> 4) << 3);
    int a_msel = (lane >> 3) & 1;
    int b_kl = lane & 15;
    int b_nsel = lane >> 4;
    int swz_k = lane & 7;       // krow&7 (k_off is a multiple of 8/16)

    int st = 0;
    for (int it = 0; it < nch; it++) {
        cp_wait<STAGES - 2>();
        __syncthreads();
        // refill (stage freed by the barrier) BEFORE mma: overlaps the MMA loop
        if (it + STAGES - 1 < nch) {
            int rst = st + (STAGES - 1);
            if (rst >= STAGES) rst -= STAGES;
            LOAD_STAGE(rst, kc0 + it + STAGES - 1);
        } else {
            cp_commit();   // keep group count in lockstep
        }

        uint32_t sA = sbase + (uint32_t)st * STAGE_BYTES;
        uint32_t sB = diag ? sA : sA + TILE_BYTES;

#pragma unroll
        for (int k = 0; k < BK / 16; k++) {
            uint32_t a[4][4];
#pragma unroll
            for (int fm = 0; fm < 4; fm++) {
                int krow = k * 16 + a_kl;
                int mch = warp_m * 8 + fm * 2 + a_msel;
                ldmatrix_x4_t(a[fm][0], a[fm][1], a[fm][2], a[fm][3],
                              sA + (uint32_t)krow * 256 +
                                   (uint32_t)((mch ^ swz_k) << 4));
            }
            uint32_t b[4][2];
#pragma unroll
            for (int fp = 0; fp < 2; fp++) {
                int krow = k * 16 + b_kl;
                int nch2 = warp_n * 4 + fp * 2 + b_nsel;
                ldmatrix_x4_t(b[fp * 2][0], b[fp * 2][1],
                              b[fp * 2 + 1][0], b[fp * 2 + 1][1],
                              sB + (uint32_t)krow * 256 +
                                   (uint32_t)((nch2 ^ swz_k) << 4));
            }
#pragma unroll
            for (int fm = 0; fm < 4; fm++)
#pragma unroll
                for (int fn = 0; fn < 4; fn++)
                    mma16816(acc[fm][fn], a[fm][0], a[fm][1], a[fm][2], a[fm][3],
                             b[fn][0], b[fn][1]);
        }
        if (++st == STAGES) st = 0;
    }

    // Epilogue: write fp32 partial tile
    float* base = &g_partials[(size_t)ks * DDIM * DDIM];
#pragma unroll
    for (int fm = 0; fm < 4; fm++) {
        int row = m0 + warp_m * 64 + fm * 16 + (lane >> 2);
#pragma unroll
        for (int fn = 0; fn < 4; fn++) {
            int col = n0 + warp_n * 32 + fn * 8 + (lane & 3) * 2;
            float* p = base + (size_t)row * DDIM + col;
            *reinterpret_cast<float2*>(p) =
                make_float2(acc[fm][fn][0], acc[fm][fn][1]);
            *reinterpret_cast<float2*>(p + 8 * DDIM) =
                make_float2(acc[fm][fn][2], acc[fm][fn][3]);
        }
    }
#undef LOAD_STAGE
}

// ============================================================================
// Kernel 3: finalize — per-subtile: sum 14 partials (batched loads for MLP),
// write direct + mirrored (smem transpose) coalesced.
// Diagonal: out_ii = KAPPA*(gram_ii - 1)  ((1-k) term cancels exactly).
// ============================================================================
__global__ void finalize_kernel(float* __restrict__ out) {
    __shared__ float trs[32][33];
    int blk = blockIdx.x;
    int pair = blk >> 4;
    int sub = blk & 15;
    int tm = c_pairs[pair * 2];
    int tn = c_pairs[pair * 2 + 1];
    int sr = sub >> 2, sc = sub & 3;
    int gi0 = tm * 128 + sr * 32;
    int gj0 = tn * 128 + sc * 32;
    int tid = threadIdx.x;
    bool diag_sub = (tm == tn) && (sr == sc);

    float p[4][KSPLIT];
#pragma unroll
    for (int q = 0; q < 4; q++) {
        int e = q * 256 + tid;
        int li = e >> 5, lj = e & 31;
        size_t off = (size_t)(gi0 + li) * DDIM + gj0 + lj;
#pragma unroll
        for (int ks = 0; ks < KSPLIT; ks++)
            p[q][ks] = g_partials[(size_t)ks * DDIM * DDIM + off];
    }

    float vals[4];
#pragma unroll
    for (int q = 0; q < 4; q++) {
        int e = q * 256 + tid;
        int li = e >> 5, lj = e & 31;
        float s = 0.f;
#pragma unroll
        for (int ks = 0; ks < KSPLIT; ks++) s += p[q][ks];
        float gme = s * (1.f / (float)NTOT);
        float v = (1.f - KAPPA) * gme - KAPPA;
        if (diag_sub && li == lj)
            v = KAPPA * (gme - 1.f);
        vals[q] = v;
        trs[li][lj] = v;
    }
    __syncthreads();
#pragma unroll
    for (int q = 0; q < 4; q++) {
        int e = q * 256 + tid;
        int li = e >> 5, lj = e & 31;
        out[(size_t)(gi0 + li) * DDIM + gj0 + lj] = vals[q];
        if (tm != tn)
            out[(size_t)(gj0 + li) * DDIM + gi0 + lj] = trs[lj][li];
    }
}

// ============================================================================
// Host launch — 2-phase overlap:
//   default: C0 -> G0 -------------------> (wait e1) G1 -> finalize
//   side   : (wait e0 after C0) C1 -> e1
// C1 (DRAM-bound) hides under G0 (mma-bound). Streams/events created once,
// outside capture; the fork/join becomes graph dependency edges.
// ============================================================================
extern "C" void kernel_launch(void* const* d_in, const int* in_sizes, int n_in,
                              void* d_out, int out_size) {
    (void)in_sizes; (void)n_in; (void)out_size;
    const float* x = (const float*)d_in[0];
    float* out = (float*)d_out;

    static cudaStream_t s1;
    static cudaEvent_t e0, e1;
    static bool init_done = false;
    if (!init_done) {
        cudaStreamCreateWithFlags(&s1, cudaStreamNonBlocking);
        cudaEventCreateWithFlags(&e0, cudaEventDisableTiming);
        cudaEventCreateWithFlags(&e1, cudaEventDisableTiming);
        cudaFuncSetAttribute(gemm_kernel, cudaFuncAttributeMaxDynamicSharedMemorySize,
                             GEMM_SMEM);
        init_done = true;
    }

    // C0: first k-half (threads 0..393215) on default stream
    convert_kernel<<<CVT_BLOCKS_HALF, 256>>>(x, 0);
    cudaEventRecord(e0, 0);

    // C1: second k-half on side stream, after C0
    cudaStreamWaitEvent(s1, e0, 0);
    convert_kernel<<<CVT_BLOCKS_HALF, 256, 0, s1>>>(x, CVT_THREADS_HALF);
    cudaEventRecord(e1, s1);

    // G0: ksplits 0..6 (k rows 0..8191) on default stream — overlaps C1
    gemm_kernel<<<NPAIRS * KGRP, 256, GEMM_SMEM>>>(0);

    // G1: ksplits 7..13 after C1 completes (and after G0 by stream order)
    cudaStreamWaitEvent(0, e1, 0);
    gemm_kernel<<<NPAIRS * KGRP, 256, GEMM_SMEM>>>(KGRP);

    // finalize
    finalize_kernel<<<NPAIRS * 16, 256>>>(out);
}

// round 13
// speedup vs baseline: 1.5491x; 1.5491x over previous
#include <cuda_runtime.h>
#include <cuda_bf16.h>
#include <cstdint>

// ============================================================================
// Problem constants
// ============================================================================
#define DDIM 768
#define NTOT 16384
#define KAPPA 0.5f

#define KSPLIT 7
#define NPAIRS 21            // 6*7/2 upper-triangle 128x128 tiles
#define BM 128
#define BK 128
#define STAGES 2
#define NCHUNK_TOT (NTOT / BK)          // 128
#define TILE_BYTES (BK * 256)           // 32 KB: [k=128][m=128] bf16, 256B rows
#define STAGE_BYTES (2 * TILE_BYTES)    // 64 KB (A + B)
#define GEMM_SMEM (STAGES * STAGE_BYTES)  // 131072

// ============================================================================
// Scratch (device globals — no allocations allowed)
// ============================================================================
__device__ __align__(1024) __nv_bfloat16 g_xbf[(size_t)NTOT * DDIM];        // 25.2 MB, same layout as x
__device__ __align__(16)   float g_partials[(size_t)KSPLIT * DDIM * DDIM];  // 16.5 MB

__constant__ unsigned char c_pairs[NPAIRS * 2] = {
    0,0, 0,1, 0,2, 0,3, 0,4, 0,5,
    1,1, 1,2, 1,3, 1,4, 1,5,
    2,2, 2,3, 2,4, 2,5,
    3,3, 3,4, 3,5,
    4,4, 4,5,
    5,5
};

// ============================================================================
// Helpers
// ============================================================================
__device__ __forceinline__ uint32_t smem_u32(const void* p) {
    uint32_t a;
    asm("{ .reg .u64 t; cvta.to.shared.u64 t, %1; cvt.u32.u64 %0, t; }" : "=r"(a) : "l"(p));
    return a;
}

__device__ __forceinline__ void cp_async16(uint32_t dst, const void* src) {
    asm volatile("cp.async.cg.shared.global [%0], [%1], 16;" :: "r"(dst), "l"(src));
}
__device__ __forceinline__ void cp_commit() {
    asm volatile("cp.async.commit_group;");
}
template <int N>
__device__ __forceinline__ void cp_wait() {
    asm volatile("cp.async.wait_group %0;" :: "n"(N));
}

__device__ __forceinline__ void ldmatrix_x4_t(uint32_t& r0, uint32_t& r1, uint32_t& r2,
                                              uint32_t& r3, uint32_t addr) {
    asm volatile("ldmatrix.sync.aligned.m8n8.x4.trans.shared.b16 {%0,%1,%2,%3}, [%4];"
                 : "=r"(r0), "=r"(r1), "=r"(r2), "=r"(r3) : "r"(addr));
}

__device__ __forceinline__ void mma16816(float* c, uint32_t a0, uint32_t a1, uint32_t a2,
                                         uint32_t a3, uint32_t b0, uint32_t b1) {
    asm volatile(
        "mma.sync.aligned.m16n8k16.row.col.f32.bf16.bf16.f32 "
        "{%0,%1,%2,%3}, {%4,%5,%6,%7}, {%8,%9}, {%0,%1,%2,%3};"
        : "+f"(c[0]), "+f"(c[1]), "+f"(c[2]), "+f"(c[3])
        : "r"(a0), "r"(a1), "r"(a2), "r"(a3), "r"(b0), "r"(b1));
}

__device__ __forceinline__ uint32_t pack_bf16x2(float lo, float hi) {
    __nv_bfloat162 p = __float22bfloat162_rn(make_float2(lo, hi));
    return *reinterpret_cast<uint32_t*>(&p);
}

// ============================================================================
// Kernel 1: pure streaming fp32 -> bf16 convert, SAME layout (no transpose).
// Bandwidth-bound: 75 MB combined traffic.
// ============================================================================
__global__ __launch_bounds__(256) void convert_kernel(const float* __restrict__ x) {
    size_t idx = (size_t)blockIdx.x * 256 + threadIdx.x;
    const float4* src = reinterpret_cast<const float4*>(x) + idx * 4;
    float4 v0 = __ldcs(src + 0);
    float4 v1 = __ldcs(src + 1);
    float4 v2 = __ldcs(src + 2);
    float4 v3 = __ldcs(src + 3);
    uint4 o0, o1;
    o0.x = pack_bf16x2(v0.x, v0.y);
    o0.y = pack_bf16x2(v0.z, v0.w);
    o0.z = pack_bf16x2(v1.x, v1.y);
    o0.w = pack_bf16x2(v1.z, v1.w);
    o1.x = pack_bf16x2(v2.x, v2.y);
    o1.y = pack_bf16x2(v2.z, v2.w);
    o1.z = pack_bf16x2(v3.x, v3.y);
    o1.w = pack_bf16x2(v3.z, v3.w);
    uint4* dst = reinterpret_cast<uint4*>(g_xbf) + idx * 2;
    dst[0] = o0;
    dst[1] = o1;
}

// ============================================================================
// Kernel 2: symmetric bf16 SYRK partials via mma.sync (HMMA).
// Grid = 21 upper-triangle tile pairs x 7 K-splits = 147 CTAs, 256 threads,
// one wave. BK=128, 2-stage double buffer (64 KB/stage): HALF the per-iter
// overhead of the BK=64/4-stage version — 18 iterations, one barrier each,
// 8 k16 MMA steps per barrier. Refill issues right after the barrier and
// overlaps the 8-step MMA run; prefetch distance = 1 full iteration.
// ============================================================================
__global__ void __launch_bounds__(256, 1) gemm_kernel() {
    extern __shared__ __align__(1024) char smem[];
    uint32_t sbase = smem_u32(smem);
    int tid = threadIdx.x;
    int lane = tid & 31;
    int wid = tid >> 5;
    int pair = blockIdx.x % NPAIRS;
    int ks = blockIdx.x / NPAIRS;
    int tm = c_pairs[pair * 2];
    int tn = c_pairs[pair * 2 + 1];
    int m0 = tm * BM;
    int n0 = tn * BM;
    bool diag = (tm == tn);
    int kc0 = (ks * NCHUNK_TOT) / KSPLIT;
    int kc1 = ((ks + 1) * NCHUNK_TOT) / KSPLIT;
    int nch = kc1 - kc0;
    int warp_m = wid & 1;       // 0..1
    int warp_n = wid >> 1;      // 0..3

    // Per stage: A tile 2048 16B-chunks (128 rows x 16 chunks), same for B.
    // chunk idx: r = idx>>4 (k-row 0..127), c = idx&15 (m/8). 8 A (+8 B)/thread.
#define LOAD_STAGE(st, kc)                                                              \
    do {                                                                                \
        uint32_t s_ = sbase + (uint32_t)(st) * STAGE_BYTES;                             \
        const __nv_bfloat16* gk = g_xbf + (size_t)((kc) * BK) * DDIM;                   \
        _Pragma("unroll")                                                               \
        for (int i_ = 0; i_ < 8; i_++) {                                                \
            int idx_ = tid + i_ * 256;                                                  \
            int r_ = idx_ >> 4, c_ = idx_ & 15;                                         \
            uint32_t off_ = (uint32_t)r_ * 256 + (uint32_t)((c_ ^ (r_ & 7)) << 4);      \
            const __nv_bfloat16* gr = gk + (size_t)r_ * DDIM + c_ * 8;                  \
            cp_async16(s_ + off_, gr + m0);                                             \
            if (!diag) cp_async16(s_ + TILE_BYTES + off_, gr + n0);                     \
        }                                                                               \
        cp_commit();                                                                    \
    } while (0)

    // prologue: fill stage 0
    LOAD_STAGE(0, kc0);

    float acc[4][4][4];
#pragma unroll
    for (int i = 0; i < 4; i++)
#pragma unroll
        for (int j = 0; j < 4; j++)
#pragma unroll
            for (int q = 0; q < 4; q++) acc[i][j][q] = 0.f;

    // ldmatrix.trans lane address components (proven in R5):
    // A frag (m16k16): krow = k_off + (l&7) + ((l>>4)<<3), mchunk = m/8 + ((l>>3)&1)
    // B frag (two n8):  krow = k_off + (l&15),             nchunk = n/8 + (l>>4)
    int a_kl = (lane & 7) + ((lane >> 4) << 3);
    int a_msel = (lane >> 3) & 1;
    int b_kl = lane & 15;
    int b_nsel = lane >> 4;
    int swz_k = lane & 7;       // krow&7 (k_off is a multiple of 16)

    for (int it = 0; it < nch; it++) {
        cp_wait<0>();
        __syncthreads();
        // refill the other stage (consumed last iter) BEFORE mma: overlaps MMA
        if (it + 1 < nch) {
            LOAD_STAGE((it + 1) & 1, kc0 + it + 1);
        }

        uint32_t sA = sbase + (uint32_t)(it & 1) * STAGE_BYTES;
        uint32_t sB = diag ? sA : sA + TILE_BYTES;

#pragma unroll
        for (int k = 0; k < BK / 16; k++) {      // 8 k16 steps
            uint32_t a[4][4];
#pragma unroll
            for (int fm = 0; fm < 4; fm++) {
                int krow = k * 16 + a_kl;
                int mch = warp_m * 8 + fm * 2 + a_msel;
                ldmatrix_x4_t(a[fm][0], a[fm][1], a[fm][2], a[fm][3],
                              sA + (uint32_t)krow * 256 +
                                   (uint32_t)((mch ^ swz_k) << 4));
            }
            uint32_t b[4][2];
#pragma unroll
            for (int fp = 0; fp < 2; fp++) {
                int krow = k * 16 + b_kl;
                int nch2 = warp_n * 4 + fp * 2 + b_nsel;
                ldmatrix_x4_t(b[fp * 2][0], b[fp * 2][1],
                              b[fp * 2 + 1][0], b[fp * 2 + 1][1],
                              sB + (uint32_t)krow * 256 +
                                   (uint32_t)((nch2 ^ swz_k) << 4));
            }
#pragma unroll
            for (int fm = 0; fm < 4; fm++)
#pragma unroll
                for (int fn = 0; fn < 4; fn++)
                    mma16816(acc[fm][fn], a[fm][0], a[fm][1], a[fm][2], a[fm][3],
                             b[fn][0], b[fn][1]);
        }
    }

    // Epilogue: write fp32 partial tile
    float* base = &g_partials[(size_t)ks * DDIM * DDIM];
#pragma unroll
    for (int fm = 0; fm < 4; fm++) {
        int row = m0 + warp_m * 64 + fm * 16 + (lane >> 2);
#pragma unroll
        for (int fn = 0; fn < 4; fn++) {
            int col = n0 + warp_n * 32 + fn * 8 + (lane & 3) * 2;
            float* p = base + (size_t)row * DDIM + col;
            *reinterpret_cast<float2*>(p) =
                make_float2(acc[fm][fn][0], acc[fm][fn][1]);
            *reinterpret_cast<float2*>(p + 8 * DDIM) =
                make_float2(acc[fm][fn][2], acc[fm][fn][3]);
        }
    }
#undef LOAD_STAGE
}

// ============================================================================
// Kernel 3: finalize — per-subtile: sum 7 partials (all 28 loads batched in
// registers for MLP), write direct + mirrored (smem transpose) coalesced.
// Diagonal: out_ii = KAPPA*(gram_ii - 1)  ((1-k) term cancels exactly).
// Grid = 21 pairs x 16 subtiles (32x32), 256 threads.
// ============================================================================
__global__ void finalize_kernel(float* __restrict__ out) {
    __shared__ float trs[32][33];
    int blk = blockIdx.x;
    int pair = blk >> 4;
    int sub = blk & 15;
    int tm = c_pairs[pair * 2];
    int tn = c_pairs[pair * 2 + 1];
    int sr = sub >> 2, sc = sub & 3;
    int gi0 = tm * 128 + sr * 32;
    int gj0 = tn * 128 + sc * 32;
    int tid = threadIdx.x;
    bool diag_sub = (tm == tn) && (sr == sc);

    float p[4][KSPLIT];
#pragma unroll
    for (int q = 0; q < 4; q++) {
        int e = q * 256 + tid;
        int li = e >> 5, lj = e & 31;
        size_t off = (size_t)(gi0 + li) * DDIM + gj0 + lj;
#pragma unroll
        for (int ks = 0; ks < KSPLIT; ks++)
            p[q][ks] = g_partials[(size_t)ks * DDIM * DDIM + off];
    }

    float vals[4];
#pragma unroll
    for (int q = 0; q < 4; q++) {
        int e = q * 256 + tid;
        int li = e >> 5, lj = e & 31;
        float s = 0.f;
#pragma unroll
        for (int ks = 0; ks < KSPLIT; ks++) s += p[q][ks];
        float gme = s * (1.f / (float)NTOT);
        float v = (1.f - KAPPA) * gme - KAPPA;
        if (diag_sub && li == lj)
            v = KAPPA * (gme - 1.f);
        vals[q] = v;
        trs[li][lj] = v;
    }
    __syncthreads();
#pragma unroll
    for (int q = 0; q < 4; q++) {
        int e = q * 256 + tid;
        int li = e >> 5, lj = e & 31;
        out[(size_t)(gi0 + li) * DDIM + gj0 + lj] = vals[q];
        if (tm != tn)
            out[(size_t)(gj0 + li) * DDIM + gi0 + lj] = trs[lj][li];
    }
}

// ============================================================================
// Host launch — single stream (R11's overlap experiment regressed; reverted)
// ============================================================================
extern "C" void kernel_launch(void* const* d_in, const int* in_sizes, int n_in,
                              void* d_out, int out_size) {
    (void)in_sizes; (void)n_in; (void)out_size;
    const float* x = (const float*)d_in[0];
    float* out = (float*)d_out;

    static bool attr_done = false;
    if (!attr_done) {
        cudaFuncSetAttribute(gemm_kernel, cudaFuncAttributeMaxDynamicSharedMemorySize,
                             GEMM_SMEM);
        attr_done = true;
    }

    // 1. streaming fp32 -> bf16 (same layout, no transpose)
    convert_kernel<<<(NTOT * DDIM) / (256 * 16), 256>>>(x);

    // 2. symmetric HMMA SYRK partials (BK=128, 2-stage)
    gemm_kernel<<<NPAIRS * KSPLIT, 256, GEMM_SMEM>>>();

    // 3. finalize
    finalize_kernel<<<NPAIRS * 16, 256>>>(out);
}